// round 2
// baseline (speedup 1.0000x reference)
#include <cuda_runtime.h>

#define HID  256
#define NG   512
#define MAXN 100000
#define MAXE 500000

// Scratch (device globals — no allocation allowed)
__device__ float g_P[(size_t)MAXN * 512];   // cols 0..255 = P1 = emb@W1_top, 256..511 = P2 = emb@W1_bot
__device__ float g_logits[MAXE];
__device__ float g_ex[MAXE];
__device__ int   g_mb[MAXE];
__device__ float g_segmax[NG];
__device__ float g_segsum[NG];
__device__ int   g_is64;                    // 1 if index buffers are int64, 0 if int32

// ---------------------------------------------------------------------------
// k-1: detect index dtype. For int64 (little-endian, values in [0, 2^31)),
// every odd 32-bit word is 0. For real int32 indices from [0, 100000), the
// odd words are actual random indices — all-zero is impossible in practice.
// Deterministic: same input bytes -> same flag.
// ---------------------------------------------------------------------------
__global__ void detect_dtype_kernel(const int* __restrict__ moves_i32) {
    int acc = 0;
#pragma unroll 8
    for (int i = 1; i < 2048; i += 2) acc |= moves_i32[i];
    g_is64 = (acc == 0) ? 1 : 0;
}

__device__ __forceinline__ long long load_idx(const void* p, size_t i, int is64) {
    if (is64) return ((const long long*)p)[i];
    return (long long)((const int*)p)[i];
}

// ---------------------------------------------------------------------------
// k0: init segment buffers
// ---------------------------------------------------------------------------
__global__ void init_seg_kernel() {
    int i = threadIdx.x;
    if (i < NG) {
        g_segmax[i] = __int_as_float(0xff800000);  // -inf
        g_segsum[i] = 0.0f;
    }
}

// ---------------------------------------------------------------------------
// k1: SGEMM  P[M, 512] = A[M,256] @ [W1_top | W1_bot]
//   BM=128, BN=128, BK=8, 256 threads, 8x8 per thread
//   grid.x = 4 column-blocks (0,1 -> W1_top cols 0..255 ; 2,3 -> W1_bot)
// ---------------------------------------------------------------------------
__global__ __launch_bounds__(256) void sgemm_kernel(
    const float* __restrict__ A, const float* __restrict__ W1, int M)
{
    const int BM = 128, BN = 128, BK = 8;
    int nblk = blockIdx.x;                       // 0..3
    int row0 = blockIdx.y * BM;
    const float* B = W1 + ((nblk >= 2) ? (256 * 256) : 0);
    int bcol0 = (nblk & 1) * BN;                 // column within the 256-wide half

    __shared__ float As[BK][BM];
    __shared__ float Bs[BK][BN];

    int tid = threadIdx.x;
    int tr = tid >> 4;                           // 0..15
    int tc = tid & 15;                           // 0..15

    float acc[8][8];
#pragma unroll
    for (int i = 0; i < 8; i++)
#pragma unroll
        for (int j = 0; j < 8; j++) acc[i][j] = 0.0f;

    int la_row = tid >> 1;                       // 0..127
    int la_k   = (tid & 1) * 4;                  // 0 or 4
    int lb_k   = tid >> 5;                       // 0..7
    int lb_col = (tid & 31) * 4;                 // 0..124

    for (int k0 = 0; k0 < HID; k0 += BK) {
        // load A tile (transposed into As[k][m]) with row guard
        float4 av = make_float4(0.f, 0.f, 0.f, 0.f);
        int grow = row0 + la_row;
        if (grow < M)
            av = *(const float4*)(A + (size_t)grow * HID + k0 + la_k);
        As[la_k + 0][la_row] = av.x;
        As[la_k + 1][la_row] = av.y;
        As[la_k + 2][la_row] = av.z;
        As[la_k + 3][la_row] = av.w;
        // load B tile (W1 half is 256x256, fits L2)
        float4 bv = *(const float4*)(B + (size_t)(k0 + lb_k) * HID + bcol0 + lb_col);
        *(float4*)&Bs[lb_k][lb_col] = bv;
        __syncthreads();

#pragma unroll
        for (int kk = 0; kk < BK; kk++) {
            float ra[8], rb[8];
            *(float4*)&ra[0] = *(const float4*)&As[kk][tr * 8];
            *(float4*)&ra[4] = *(const float4*)&As[kk][tr * 8 + 4];
            *(float4*)&rb[0] = *(const float4*)&Bs[kk][tc * 8];
            *(float4*)&rb[4] = *(const float4*)&Bs[kk][tc * 8 + 4];
#pragma unroll
            for (int i = 0; i < 8; i++)
#pragma unroll
                for (int j = 0; j < 8; j++)
                    acc[i][j] += ra[i] * rb[j];
        }
        __syncthreads();
    }

    int gcol = nblk * BN + tc * 8;               // 0..511
#pragma unroll
    for (int i = 0; i < 8; i++) {
        int r = row0 + tr * 8 + i;
        if (r < M) {
            float* dst = g_P + (size_t)r * 512 + gcol;
            *(float4*)dst       = make_float4(acc[i][0], acc[i][1], acc[i][2], acc[i][3]);
            *(float4*)(dst + 4) = make_float4(acc[i][4], acc[i][5], acc[i][6], acc[i][7]);
        }
    }
}

// ---------------------------------------------------------------------------
// float atomic max (sign-split trick; correct for mixed signs incl. -inf init)
// ---------------------------------------------------------------------------
__device__ __forceinline__ void atomicMaxF(float* a, float v) {
    if (v >= 0.0f) atomicMax((int*)a, __float_as_int(v));
    else           atomicMin((unsigned int*)a, __float_as_uint(v));
}

// ---------------------------------------------------------------------------
// k2: warp-per-move gather + ReLU + dot(W2) -> logits, move_batch, seg max
// ---------------------------------------------------------------------------
__global__ __launch_bounds__(256) void gather_logits_kernel(
    const void* __restrict__ moves,           // [2, NM] int32 or int64
    const void* __restrict__ batch,           // [N]    int32 or int64
    const float* __restrict__ b1,             // [256]
    const float* __restrict__ W2,             // [256]
    const float* __restrict__ b2,             // [1]
    int NM)
{
    int warp = (blockIdx.x * blockDim.x + threadIdx.x) >> 5;
    int lane = threadIdx.x & 31;
    if (warp >= NM) return;

    int is64 = g_is64;
    long long s = load_idx(moves, warp, is64);
    long long t = load_idx(moves, (size_t)NM + warp, is64);

    const float4* p1 = (const float4*)(g_P + (size_t)s * 512);        // P1 row s
    const float4* p2 = (const float4*)(g_P + (size_t)t * 512 + 256);  // P2 row t
    const float4* bb = (const float4*)b1;
    const float4* ww = (const float4*)W2;

    float acc = 0.0f;
#pragma unroll
    for (int q = 0; q < 2; q++) {
        int idx = lane * 2 + q;                // covers j = lane*8 .. lane*8+7
        float4 a = p1[idx];
        float4 b = p2[idx];
        float4 c = bb[idx];
        float4 w = ww[idx];
        acc += fmaxf(a.x + b.x + c.x, 0.0f) * w.x;
        acc += fmaxf(a.y + b.y + c.y, 0.0f) * w.y;
        acc += fmaxf(a.z + b.z + c.z, 0.0f) * w.z;
        acc += fmaxf(a.w + b.w + c.w, 0.0f) * w.w;
    }
#pragma unroll
    for (int o = 16; o; o >>= 1) acc += __shfl_xor_sync(0xffffffffu, acc, o);

    if (lane == 0) {
        float logit = acc + b2[0];
        int g = (int)load_idx(batch, (size_t)s, is64);
        g_logits[warp] = logit;
        g_mb[warp] = g;
        atomicMaxF(&g_segmax[g], logit);
    }
}

// ---------------------------------------------------------------------------
// k3: ex = exp(logit - segmax), seg sum
// ---------------------------------------------------------------------------
__global__ void exp_kernel(int NM) {
    int i = blockIdx.x * blockDim.x + threadIdx.x;
    if (i < NM) {
        int g = g_mb[i];
        float e = expf(g_logits[i] - g_segmax[g]);
        g_ex[i] = e;
        atomicAdd(&g_segsum[g], e);
    }
}

// ---------------------------------------------------------------------------
// k4: probs = ex / (segsum + eps)
// ---------------------------------------------------------------------------
__global__ void div_kernel(float* __restrict__ out, int NM) {
    int i = blockIdx.x * blockDim.x + threadIdx.x;
    if (i < NM) {
        out[i] = g_ex[i] / (g_segsum[g_mb[i]] + 1e-16f);
    }
}

// ---------------------------------------------------------------------------
extern "C" void kernel_launch(void* const* d_in, const int* in_sizes, int n_in,
                              void* d_out, int out_size)
{
    const float* emb   = (const float*)d_in[0];
    const void*  moves = d_in[1];
    const void*  batch = d_in[2];
    const float* W1    = (const float*)d_in[3];
    const float* b1    = (const float*)d_in[4];
    const float* W2    = (const float*)d_in[5];
    const float* b2    = (const float*)d_in[6];

    int M  = in_sizes[0] / HID;   // 100000
    int NM = in_sizes[1] / 2;     // 500000

    detect_dtype_kernel<<<1, 1>>>((const int*)moves);
    init_seg_kernel<<<1, NG>>>();

    dim3 ggrid(4, (M + 127) / 128);
    sgemm_kernel<<<ggrid, 256>>>(emb, W1, M);

    int warps_per_block = 256 / 32;
    int gblocks = (NM + warps_per_block - 1) / warps_per_block;
    gather_logits_kernel<<<gblocks, 256>>>(moves, batch, b1, W2, b2, NM);

    exp_kernel<<<(NM + 255) / 256, 256>>>(NM);
    div_kernel<<<(NM + 255) / 256, 256>>>((float*)d_out, NM);
}

// round 3
// speedup vs baseline: 1.0416x; 1.0416x over previous
#include <cuda_runtime.h>
#include <cuda_fp16.h>

#define HID  256
#define NG   512
#define MAXN 100000
#define MAXE 500000

// Scratch (device globals)
__device__ __half g_Ph[(size_t)MAXN * 512];   // fp16: cols 0..255 = P1, 256..511 = P2
__device__ float  g_logits[MAXE];
__device__ float  g_ex[MAXE];
__device__ int    g_mb[MAXE];
__device__ float  g_segmax[NG];
__device__ float  g_segsum[NG];
__device__ int    g_is64;

// ---------------------------------------------------------------------------
// detect index dtype (int64 => all odd 32-bit words zero for values < 2^31)
// ---------------------------------------------------------------------------
__global__ void detect_dtype_kernel(const int* __restrict__ moves_i32) {
    int acc = 0;
#pragma unroll 8
    for (int i = 1; i < 2048; i += 2) acc |= moves_i32[i];
    g_is64 = (acc == 0) ? 1 : 0;
}

__device__ __forceinline__ long long load_idx(const void* p, size_t i, int is64) {
    if (is64) return ((const long long*)p)[i];
    return (long long)((const int*)p)[i];
}

__global__ void init_seg_kernel() {
    int i = threadIdx.x;
    if (i < NG) {
        g_segmax[i] = __int_as_float(0xff800000);
        g_segsum[i] = 0.0f;
    }
}

// ---------------------------------------------------------------------------
// tf32 GEMM: P[M, 512] = A[M,256] @ [W1_top | W1_bot], output fp16
//   BM=128 BN=128 BK=32, 256 threads (8 warps), warp tile 64x32 via m16n8k8.
//   Smem holds tiles pre-shuffled into mma fragment order:
//     sA[ks(4)][mtile(8)][lane(32)][reg(4)]  (16 KB)
//     sB[ks(4)][ntile(16)][lane(32)][reg(2)] (16 KB)
//   grid.x = 4 column blocks (0,1 -> W1_top, 2,3 -> W1_bot)
// ---------------------------------------------------------------------------
__device__ __forceinline__ unsigned f2tf32(float x) {
    unsigned r;
    asm("cvt.rna.tf32.f32 %0, %1;" : "=r"(r) : "f"(x));
    return r;
}

__global__ __launch_bounds__(256, 1) void tf32_gemm_kernel(
    const float* __restrict__ A, const float* __restrict__ W1, int M)
{
    const int BM = 128, BN = 128, BK = 32;
    int nblk = blockIdx.x;                 // 0..3
    int row0 = blockIdx.y * BM;
    const float* B = W1 + ((nblk >= 2) ? (256 * 256) : 0);
    int bcol0 = (nblk & 1) * BN;

    __shared__ unsigned sA[4 * 8 * 32 * 4];    // 4096 words
    __shared__ unsigned sB[4 * 16 * 32 * 2];   // 4096 words

    int tid  = threadIdx.x;
    int lane = tid & 31;
    int wid  = tid >> 5;
    int wm   = wid & 1;                    // 0..1 (64-row halves)
    int wn   = wid >> 1;                   // 0..3 (32-col quarters)

    float acc[4][4][4];
#pragma unroll
    for (int i = 0; i < 4; i++)
#pragma unroll
        for (int j = 0; j < 4; j++)
#pragma unroll
            for (int r = 0; r < 4; r++) acc[i][j][r] = 0.0f;

    // prefetch registers: 4 float4 for A, 4 float4 for B
    float4 pa[4], pb[4];

    // loader indices (constant across iterations)
    int fa_m[4], fa_k[4], fb_k[4], fb_n[4];
#pragma unroll
    for (int i = 0; i < 4; i++) {
        int f = tid + 256 * i;             // 0..1023
        fa_m[i] = f >> 3;                  // 0..127
        fa_k[i] = (f & 7) * 4;             // 0..28
        fb_k[i] = f >> 5;                  // 0..31
        fb_n[i] = (f & 31) * 4;            // 0..124
    }

    // --- prefetch k0 = 0 ---
#pragma unroll
    for (int i = 0; i < 4; i++) {
        int grow = row0 + fa_m[i];
        pa[i] = (grow < M) ? *(const float4*)(A + (size_t)grow * HID + fa_k[i])
                           : make_float4(0.f, 0.f, 0.f, 0.f);
        pb[i] = *(const float4*)(B + (size_t)fb_k[i] * HID + bcol0 + fb_n[i]);
    }

    for (int kt = 0; kt < 8; kt++) {
        if (kt) __syncthreads();           // previous tile fully consumed

        // store prefetched tile to shuffled smem (with tf32 convert)
#pragma unroll
        for (int i = 0; i < 4; i++) {
            float av[4] = {pa[i].x, pa[i].y, pa[i].z, pa[i].w};
            int m = fa_m[i];
            int mt = m >> 4, rin = m & 15, g = rin & 7;
#pragma unroll
            for (int e = 0; e < 4; e++) {
                int kk = fa_k[i] + e;
                int ks = kk >> 3;
                int reg = (((kk & 7) >= 4) ? 2 : 0) + ((rin >= 8) ? 1 : 0);
                int ln = g * 4 + (kk & 3);
                sA[((ks * 8 + mt) * 32 + ln) * 4 + reg] = f2tf32(av[e]);
            }
            float bv[4] = {pb[i].x, pb[i].y, pb[i].z, pb[i].w};
            int k = fb_k[i];
            int ks = k >> 3;
            int regb = ((k & 7) >= 4) ? 1 : 0;
#pragma unroll
            for (int e = 0; e < 4; e++) {
                int nn = fb_n[i] + e;
                int nt = nn >> 3;
                int ln = (nn & 7) * 4 + (k & 3);
                sB[((ks * 16 + nt) * 32 + ln) * 2 + regb] = f2tf32(bv[e]);
            }
        }
        __syncthreads();

        // prefetch next tile
        if (kt < 7) {
            int k0 = (kt + 1) * BK;
#pragma unroll
            for (int i = 0; i < 4; i++) {
                int grow = row0 + fa_m[i];
                pa[i] = (grow < M) ? *(const float4*)(A + (size_t)grow * HID + k0 + fa_k[i])
                                   : make_float4(0.f, 0.f, 0.f, 0.f);
                pb[i] = *(const float4*)(B + (size_t)(k0 + fb_k[i]) * HID + bcol0 + fb_n[i]);
            }
        }

        // compute
#pragma unroll
        for (int ks = 0; ks < 4; ks++) {
            uint4 af[4];
            uint2 bf[4];
#pragma unroll
            for (int mt = 0; mt < 4; mt++)
                af[mt] = *(const uint4*)&sA[((ks * 8 + wm * 4 + mt) * 32 + lane) * 4];
#pragma unroll
            for (int nt = 0; nt < 4; nt++)
                bf[nt] = *(const uint2*)&sB[((ks * 16 + wn * 4 + nt) * 32 + lane) * 2];
#pragma unroll
            for (int mt = 0; mt < 4; mt++)
#pragma unroll
                for (int nt = 0; nt < 4; nt++) {
                    asm volatile(
                        "mma.sync.aligned.m16n8k8.row.col.f32.tf32.tf32.f32 "
                        "{%0,%1,%2,%3}, {%4,%5,%6,%7}, {%8,%9}, {%0,%1,%2,%3};"
                        : "+f"(acc[mt][nt][0]), "+f"(acc[mt][nt][1]),
                          "+f"(acc[mt][nt][2]), "+f"(acc[mt][nt][3])
                        : "r"(af[mt].x), "r"(af[mt].y), "r"(af[mt].z), "r"(af[mt].w),
                          "r"(bf[nt].x), "r"(bf[nt].y));
                }
        }
    }

    // epilogue: fp16 store. c0,c1 at (row, 2c..2c+1), c2,c3 at (row+8).
    int gcol_base = nblk * BN + wn * 32 + (lane & 3) * 2;
    int grow_base = row0 + wm * 64 + (lane >> 2);
#pragma unroll
    for (int mt = 0; mt < 4; mt++) {
#pragma unroll
        for (int nt = 0; nt < 4; nt++) {
            int gc = gcol_base + nt * 8;
            int r0 = grow_base + mt * 16;
            if (r0 < M)
                *(__half2*)(g_Ph + (size_t)r0 * 512 + gc) =
                    __floats2half2_rn(acc[mt][nt][0], acc[mt][nt][1]);
            if (r0 + 8 < M)
                *(__half2*)(g_Ph + (size_t)(r0 + 8) * 512 + gc) =
                    __floats2half2_rn(acc[mt][nt][2], acc[mt][nt][3]);
        }
    }
}

// ---------------------------------------------------------------------------
__device__ __forceinline__ void atomicMaxF(float* a, float v) {
    if (v >= 0.0f) atomicMax((int*)a, __float_as_int(v));
    else           atomicMin((unsigned int*)a, __float_as_uint(v));
}

// ---------------------------------------------------------------------------
// gather: warp per move, fp16 P rows (512B each side)
// ---------------------------------------------------------------------------
__global__ __launch_bounds__(256) void gather_logits_kernel(
    const void* __restrict__ moves,
    const void* __restrict__ batch,
    const float* __restrict__ b1,
    const float* __restrict__ W2,
    const float* __restrict__ b2,
    int NM)
{
    int warp = (blockIdx.x * blockDim.x + threadIdx.x) >> 5;
    int lane = threadIdx.x & 31;
    if (warp >= NM) return;

    int is64 = g_is64;
    long long s = load_idx(moves, warp, is64);
    long long t = load_idx(moves, (size_t)NM + warp, is64);

    // lane covers j = lane*8 .. lane*8+7
    uint4 u1 = ((const uint4*)(g_Ph + (size_t)s * 512))[lane];
    uint4 u2 = ((const uint4*)(g_Ph + (size_t)t * 512 + 256))[lane];
    float4 c0 = ((const float4*)b1)[lane * 2];
    float4 c1 = ((const float4*)b1)[lane * 2 + 1];
    float4 w0 = ((const float4*)W2)[lane * 2];
    float4 w1 = ((const float4*)W2)[lane * 2 + 1];

    float2 a0 = __half22float2(*(const __half2*)&u1.x);
    float2 a1 = __half22float2(*(const __half2*)&u1.y);
    float2 a2 = __half22float2(*(const __half2*)&u1.z);
    float2 a3 = __half22float2(*(const __half2*)&u1.w);
    float2 d0 = __half22float2(*(const __half2*)&u2.x);
    float2 d1 = __half22float2(*(const __half2*)&u2.y);
    float2 d2 = __half22float2(*(const __half2*)&u2.z);
    float2 d3 = __half22float2(*(const __half2*)&u2.w);

    float acc = 0.0f;
    acc += fmaxf(a0.x + d0.x + c0.x, 0.0f) * w0.x;
    acc += fmaxf(a0.y + d0.y + c0.y, 0.0f) * w0.y;
    acc += fmaxf(a1.x + d1.x + c0.z, 0.0f) * w0.z;
    acc += fmaxf(a1.y + d1.y + c0.w, 0.0f) * w0.w;
    acc += fmaxf(a2.x + d2.x + c1.x, 0.0f) * w1.x;
    acc += fmaxf(a2.y + d2.y + c1.y, 0.0f) * w1.y;
    acc += fmaxf(a3.x + d3.x + c1.z, 0.0f) * w1.z;
    acc += fmaxf(a3.y + d3.y + c1.w, 0.0f) * w1.w;

#pragma unroll
    for (int o = 16; o; o >>= 1) acc += __shfl_xor_sync(0xffffffffu, acc, o);

    if (lane == 0) {
        float logit = acc + b2[0];
        int g = (int)load_idx(batch, (size_t)s, is64);
        g_logits[warp] = logit;
        g_mb[warp] = g;
        atomicMaxF(&g_segmax[g], logit);
    }
}

__global__ void exp_kernel(int NM) {
    int i = blockIdx.x * blockDim.x + threadIdx.x;
    if (i < NM) {
        int g = g_mb[i];
        float e = expf(g_logits[i] - g_segmax[g]);
        g_ex[i] = e;
        atomicAdd(&g_segsum[g], e);
    }
}

__global__ void div_kernel(float* __restrict__ out, int NM) {
    int i = blockIdx.x * blockDim.x + threadIdx.x;
    if (i < NM) {
        out[i] = g_ex[i] / (g_segsum[g_mb[i]] + 1e-16f);
    }
}

// ---------------------------------------------------------------------------
extern "C" void kernel_launch(void* const* d_in, const int* in_sizes, int n_in,
                              void* d_out, int out_size)
{
    const float* emb   = (const float*)d_in[0];
    const void*  moves = d_in[1];
    const void*  batch = d_in[2];
    const float* W1    = (const float*)d_in[3];
    const float* b1    = (const float*)d_in[4];
    const float* W2    = (const float*)d_in[5];
    const float* b2    = (const float*)d_in[6];

    int M  = in_sizes[0] / HID;   // 100000
    int NM = in_sizes[1] / 2;     // 500000

    detect_dtype_kernel<<<1, 1>>>((const int*)moves);
    init_seg_kernel<<<1, NG>>>();

    dim3 ggrid(4, (M + 127) / 128);
    tf32_gemm_kernel<<<ggrid, 256>>>(emb, W1, M);

    int gblocks = (NM + 7) / 8;
    gather_logits_kernel<<<gblocks, 256>>>(moves, batch, b1, W2, b2, NM);

    exp_kernel<<<(NM + 255) / 256, 256>>>(NM);
    div_kernel<<<(NM + 255) / 256, 256>>>((float*)d_out, NM);
}

// round 7
// speedup vs baseline: 2.4323x; 2.3352x over previous
#include <cuda_runtime.h>
#include <cuda_fp16.h>

#define HID  256
#define NG   512
#define MAXN 100000
#define MAXE 500000
#define PADK 40            // padded smem row stride in fp16 (32 data + 8 pad = 80 B)

// Scratch (device globals)
__device__ __half g_Ah[(size_t)MAXN * HID];    // emb in fp16
__device__ __half g_W1h[512 * 256];            // W1 transposed: [(h*256+n)][k]
__device__ __half g_Ph[(size_t)MAXN * 512];    // P: cols 0..255 = P1, 256..511 = P2
__device__ float  g_logits[MAXE];
__device__ float  g_ex[MAXE];
__device__ int    g_mb[MAXE];
__device__ float  g_segmax[NG];
__device__ float  g_segsum[NG];
__device__ int    g_is64;

// ---------------------------------------------------------------------------
__global__ void detect_dtype_kernel(const int* __restrict__ moves_i32) {
    int acc = 0;
#pragma unroll 8
    for (int i = 1; i < 2048; i += 2) acc |= moves_i32[i];
    g_is64 = (acc == 0) ? 1 : 0;
}

__device__ __forceinline__ long long load_idx(const void* p, size_t i, int is64) {
    if (is64) return ((const long long*)p)[i];
    return (long long)((const int*)p)[i];
}

__global__ void init_seg_kernel() {
    int i = threadIdx.x;
    if (i < NG) {
        g_segmax[i] = __int_as_float(0xff800000);
        g_segsum[i] = 0.0f;
    }
}

// ---------------------------------------------------------------------------
// convert emb -> fp16 (vectorized), W1 -> fp16 transposed [n][k]
// ---------------------------------------------------------------------------
__global__ void convert_A_kernel(const float* __restrict__ A, int n4) {
    int i = blockIdx.x * blockDim.x + threadIdx.x;
    if (i < n4) {
        float4 v = ((const float4*)A)[i];
        __half2* dst = (__half2*)g_Ah + (size_t)i * 2;
        dst[0] = __floats2half2_rn(v.x, v.y);
        dst[1] = __floats2half2_rn(v.z, v.w);
    }
}

__global__ void convert_W1_kernel(const float* __restrict__ W1) {
    int e = blockIdx.x * blockDim.x + threadIdx.x;   // 0 .. 512*256-1
    if (e < 512 * 256) {
        int r = e >> 8;          // W1 row (feature index) 0..511
        int n = e & 255;         // W1 col (output j)
        int h = r >> 8;          // half 0/1
        int k = r & 255;         // k within half
        g_W1h[(h * 256 + n) * 256 + k] = __float2half(W1[e]);
    }
}

// ---------------------------------------------------------------------------
// fp16 GEMM: P[M, 512] = Ah[M,256] @ W1h^T, output fp16
//   BM=128 BN=128 BK=32, 256 threads / 8 warps, warp tile 64x32, m16n8k16.
//   cp.async double-buffered STATIC smem (40 KB), padded stride 40, ldmatrix.
//   grid.x = 4 column blocks of 128 P-columns.
// ---------------------------------------------------------------------------
__device__ __forceinline__ unsigned smem_u32(const void* p) {
    return (unsigned)__cvta_generic_to_shared(p);
}

__global__ __launch_bounds__(256) void hgemm_kernel(int M) {
    __shared__ __half As[2][128 * PADK];
    __shared__ __half Bs[2][128 * PADK];

    int nblk = blockIdx.x;                  // 0..3 -> P cols [nblk*128, +128)
    int row0 = blockIdx.y * 128;
    int tid  = threadIdx.x;
    int lane = tid & 31;
    int wid  = tid >> 5;
    int wm   = wid & 1;                     // 64-row half
    int wn   = wid >> 1;                    // 32-col quarter

    // loader: tile = 128 rows x 32 halves = 512 16B-chunks; 2 per thread
    int lrow[2], lcol[2];
#pragma unroll
    for (int i = 0; i < 2; i++) {
        int c = tid + 256 * i;
        lrow[i] = c >> 2;                   // 0..127
        lcol[i] = (c & 3) * 8;              // 0,8,16,24
    }

    const __half* Bsrc = g_W1h + (size_t)(nblk * 128) * 256;

    auto issue_tile = [&](int kt) {
        int s = kt & 1;
        int kb = kt * 32;
#pragma unroll
        for (int i = 0; i < 2; i++) {
            {
                unsigned dst = smem_u32(&As[s][lrow[i] * PADK + lcol[i]]);
                const __half* src = g_Ah + (size_t)(row0 + lrow[i]) * HID + kb + lcol[i];
                int sz = (row0 + lrow[i] < M) ? 16 : 0;
                asm volatile("cp.async.cg.shared.global [%0], [%1], 16, %2;\n"
                             :: "r"(dst), "l"(src), "r"(sz));
            }
            {
                unsigned dst = smem_u32(&Bs[s][lrow[i] * PADK + lcol[i]]);
                const __half* src = Bsrc + (size_t)lrow[i] * 256 + kb + lcol[i];
                asm volatile("cp.async.cg.shared.global [%0], [%1], 16;\n"
                             :: "r"(dst), "l"(src));
            }
        }
        asm volatile("cp.async.commit_group;\n");
    };

    float acc[4][4][4];
#pragma unroll
    for (int i = 0; i < 4; i++)
#pragma unroll
        for (int j = 0; j < 4; j++)
#pragma unroll
            for (int r = 0; r < 4; r++) acc[i][j][r] = 0.0f;

    issue_tile(0);

    for (int kt = 0; kt < 8; kt++) {
        if (kt < 7) {
            issue_tile(kt + 1);
            asm volatile("cp.async.wait_group 1;\n");
        } else {
            asm volatile("cp.async.wait_group 0;\n");
        }
        __syncthreads();

        int s = kt & 1;
        const __half* Asb = &As[s][wm * 64 * PADK];
        const __half* Bsb = &Bs[s][wn * 32 * PADK];

#pragma unroll
        for (int ks = 0; ks < 2; ks++) {
            int kb = ks * 16;
            unsigned af[4][4];
            unsigned bf[4][2];
#pragma unroll
            for (int mt = 0; mt < 4; mt++) {
                unsigned addr = smem_u32(Asb + (mt * 16 + (lane & 15)) * PADK + kb + (lane >> 4) * 8);
                asm volatile("ldmatrix.sync.aligned.m8n8.x4.shared.b16 {%0,%1,%2,%3}, [%4];\n"
                             : "=r"(af[mt][0]), "=r"(af[mt][1]), "=r"(af[mt][2]), "=r"(af[mt][3])
                             : "r"(addr));
            }
#pragma unroll
            for (int nt = 0; nt < 4; nt++) {
                unsigned addr = smem_u32(Bsb + (nt * 8 + (lane & 7)) * PADK + kb + ((lane >> 3) & 1) * 8);
                asm volatile("ldmatrix.sync.aligned.m8n8.x2.shared.b16 {%0,%1}, [%2];\n"
                             : "=r"(bf[nt][0]), "=r"(bf[nt][1])
                             : "r"(addr));
            }
#pragma unroll
            for (int mt = 0; mt < 4; mt++)
#pragma unroll
                for (int nt = 0; nt < 4; nt++) {
                    asm volatile(
                        "mma.sync.aligned.m16n8k16.row.col.f32.f16.f16.f32 "
                        "{%0,%1,%2,%3}, {%4,%5,%6,%7}, {%8,%9}, {%0,%1,%2,%3};\n"
                        : "+f"(acc[mt][nt][0]), "+f"(acc[mt][nt][1]),
                          "+f"(acc[mt][nt][2]), "+f"(acc[mt][nt][3])
                        : "r"(af[mt][0]), "r"(af[mt][1]), "r"(af[mt][2]), "r"(af[mt][3]),
                          "r"(bf[nt][0]), "r"(bf[nt][1]));
                }
        }
        __syncthreads();
    }

    // epilogue: fp16 store to g_Ph (m16n8 frag layout)
    int gcol_base = nblk * 128 + wn * 32 + (lane & 3) * 2;
    int grow_base = row0 + wm * 64 + (lane >> 2);
#pragma unroll
    for (int mt = 0; mt < 4; mt++) {
#pragma unroll
        for (int nt = 0; nt < 4; nt++) {
            int gc = gcol_base + nt * 8;
            int r0 = grow_base + mt * 16;
            if (r0 < M)
                *(__half2*)(g_Ph + (size_t)r0 * 512 + gc) =
                    __floats2half2_rn(acc[mt][nt][0], acc[mt][nt][1]);
            if (r0 + 8 < M)
                *(__half2*)(g_Ph + (size_t)(r0 + 8) * 512 + gc) =
                    __floats2half2_rn(acc[mt][nt][2], acc[mt][nt][3]);
        }
    }
}

// ---------------------------------------------------------------------------
__device__ __forceinline__ void atomicMaxF(float* a, float v) {
    if (v >= 0.0f) atomicMax((int*)a, __float_as_int(v));
    else           atomicMin((unsigned int*)a, __float_as_uint(v));
}

// ---------------------------------------------------------------------------
// gather: warp per move, fp16 P rows
// ---------------------------------------------------------------------------
__global__ __launch_bounds__(256) void gather_logits_kernel(
    const void* __restrict__ moves,
    const void* __restrict__ batch,
    const float* __restrict__ b1,
    const float* __restrict__ W2,
    const float* __restrict__ b2,
    int NM)
{
    int warp = (blockIdx.x * blockDim.x + threadIdx.x) >> 5;
    int lane = threadIdx.x & 31;
    if (warp >= NM) return;

    int is64 = g_is64;
    long long s = load_idx(moves, warp, is64);
    long long t = load_idx(moves, (size_t)NM + warp, is64);

    uint4 u1 = ((const uint4*)(g_Ph + (size_t)s * 512))[lane];
    uint4 u2 = ((const uint4*)(g_Ph + (size_t)t * 512 + 256))[lane];
    float4 c0 = ((const float4*)b1)[lane * 2];
    float4 c1 = ((const float4*)b1)[lane * 2 + 1];
    float4 w0 = ((const float4*)W2)[lane * 2];
    float4 w1 = ((const float4*)W2)[lane * 2 + 1];

    float2 a0 = __half22float2(*(const __half2*)&u1.x);
    float2 a1 = __half22float2(*(const __half2*)&u1.y);
    float2 a2 = __half22float2(*(const __half2*)&u1.z);
    float2 a3 = __half22float2(*(const __half2*)&u1.w);
    float2 d0 = __half22float2(*(const __half2*)&u2.x);
    float2 d1 = __half22float2(*(const __half2*)&u2.y);
    float2 d2 = __half22float2(*(const __half2*)&u2.z);
    float2 d3 = __half22float2(*(const __half2*)&u2.w);

    float acc = 0.0f;
    acc += fmaxf(a0.x + d0.x + c0.x, 0.0f) * w0.x;
    acc += fmaxf(a0.y + d0.y + c0.y, 0.0f) * w0.y;
    acc += fmaxf(a1.x + d1.x + c0.z, 0.0f) * w0.z;
    acc += fmaxf(a1.y + d1.y + c0.w, 0.0f) * w0.w;
    acc += fmaxf(a2.x + d2.x + c1.x, 0.0f) * w1.x;
    acc += fmaxf(a2.y + d2.y + c1.y, 0.0f) * w1.y;
    acc += fmaxf(a3.x + d3.x + c1.z, 0.0f) * w1.z;
    acc += fmaxf(a3.y + d3.y + c1.w, 0.0f) * w1.w;

#pragma unroll
    for (int o = 16; o; o >>= 1) acc += __shfl_xor_sync(0xffffffffu, acc, o);

    if (lane == 0) {
        float logit = acc + b2[0];
        int g = (int)load_idx(batch, (size_t)s, is64);
        g_logits[warp] = logit;
        g_mb[warp] = g;
        atomicMaxF(&g_segmax[g], logit);
    }
}

__global__ void exp_kernel(int NM) {
    int i = blockIdx.x * blockDim.x + threadIdx.x;
    if (i < NM) {
        int g = g_mb[i];
        float e = expf(g_logits[i] - g_segmax[g]);
        g_ex[i] = e;
        atomicAdd(&g_segsum[g], e);
    }
}

__global__ void div_kernel(float* __restrict__ out, int NM) {
    int i = blockIdx.x * blockDim.x + threadIdx.x;
    if (i < NM) {
        out[i] = g_ex[i] / (g_segsum[g_mb[i]] + 1e-16f);
    }
}

// ---------------------------------------------------------------------------
extern "C" void kernel_launch(void* const* d_in, const int* in_sizes, int n_in,
                              void* d_out, int out_size)
{
    const float* emb   = (const float*)d_in[0];
    const void*  moves = d_in[1];
    const void*  batch = d_in[2];
    const float* W1    = (const float*)d_in[3];
    const float* b1    = (const float*)d_in[4];
    const float* W2    = (const float*)d_in[5];
    const float* b2    = (const float*)d_in[6];

    int M  = in_sizes[0] / HID;   // 100000
    int NM = in_sizes[1] / 2;     // 500000

    detect_dtype_kernel<<<1, 1>>>((const int*)moves);
    init_seg_kernel<<<1, NG>>>();

    int n4 = M * HID / 4;
    convert_A_kernel<<<(n4 + 255) / 256, 256>>>(emb, n4);
    convert_W1_kernel<<<(512 * 256 + 255) / 256, 256>>>(W1);

    dim3 ggrid(4, (M + 127) / 128);
    hgemm_kernel<<<ggrid, 256>>>(M);

    int gblocks = (NM + 7) / 8;
    gather_logits_kernel<<<gblocks, 256>>>(moves, batch, b1, W2, b2, NM);

    exp_kernel<<<(NM + 255) / 256, 256>>>(NM);
    div_kernel<<<(NM + 255) / 256, 256>>>((float*)d_out, NM);
}

// round 9
// speedup vs baseline: 2.5896x; 1.0647x over previous
#include <cuda_runtime.h>
#include <cuda_fp16.h>

#define HID  256
#define NG   512
#define MAXN 100000
#define MAXE 500000
#define PADK 40            // padded smem row stride in fp16 (32 data + 8 pad = 80 B)

// Scratch (device globals)
__device__ __half g_Ah[(size_t)MAXN * HID];    // emb in fp16
__device__ __half g_W1h[512 * 256];            // W1 transposed: [(h*256+n)][k]
__device__ __half g_W2h[256];                  // W2 in fp16
__device__ __half g_Ph[(size_t)MAXN * 512];    // P: cols 0..255 = P1+b1, 256..511 = P2
__device__ float  g_logits[MAXE];
__device__ int    g_mb[MAXE];
__device__ float  g_segmax[NG];
__device__ float  g_segsum[NG];
__device__ int    g_is64;

// ---------------------------------------------------------------------------
__global__ void detect_dtype_kernel(const int* __restrict__ moves_i32) {
    int acc = 0;
#pragma unroll 8
    for (int i = 1; i < 2048; i += 2) acc |= moves_i32[i];
    g_is64 = (acc == 0) ? 1 : 0;
}

__device__ __forceinline__ long long load_idx(const void* p, size_t i, int is64) {
    if (is64) return ((const long long*)p)[i];
    return (long long)((const int*)p)[i];
}

__global__ void init_seg_kernel() {
    int i = threadIdx.x;
    if (i < NG) {
        g_segmax[i] = __int_as_float(0xff800000);
        g_segsum[i] = 0.0f;
    }
}

// ---------------------------------------------------------------------------
// converts: emb -> fp16, W1 -> fp16 transposed [n][k], W2 -> fp16
// ---------------------------------------------------------------------------
__global__ void convert_A_kernel(const float* __restrict__ A, int n4) {
    int i = blockIdx.x * blockDim.x + threadIdx.x;
    if (i < n4) {
        float4 v = ((const float4*)A)[i];
        __half2* dst = (__half2*)g_Ah + (size_t)i * 2;
        dst[0] = __floats2half2_rn(v.x, v.y);
        dst[1] = __floats2half2_rn(v.z, v.w);
    }
}

__global__ void convert_W1_kernel(const float* __restrict__ W1,
                                  const float* __restrict__ W2) {
    int e = blockIdx.x * blockDim.x + threadIdx.x;   // 0 .. 512*256-1
    if (e < 512 * 256) {
        int r = e >> 8;          // W1 row (feature index) 0..511
        int n = e & 255;         // W1 col (output j)
        int h = r >> 8;          // half 0/1
        int k = r & 255;         // k within half
        g_W1h[(h * 256 + n) * 256 + k] = __float2half(W1[e]);
    }
    if (e < 256) g_W2h[e] = __float2half(W2[e]);
}

// ---------------------------------------------------------------------------
// fp16 GEMM: P[M, 512] = Ah[M,256] @ W1h^T (+ b1 on cols 0..255), output fp16
//   BM=128 BN=128 BK=32, 256 threads / 8 warps, warp tile 64x32, m16n8k16.
//   cp.async double-buffered STATIC smem (40 KB), padded stride 40, ldmatrix.
// ---------------------------------------------------------------------------
__device__ __forceinline__ unsigned smem_u32(const void* p) {
    return (unsigned)__cvta_generic_to_shared(p);
}

__global__ __launch_bounds__(256) void hgemm_kernel(const float* __restrict__ b1, int M) {
    __shared__ __half As[2][128 * PADK];
    __shared__ __half Bs[2][128 * PADK];

    int nblk = blockIdx.x;                  // 0..3 -> P cols [nblk*128, +128)
    int row0 = blockIdx.y * 128;
    int tid  = threadIdx.x;
    int lane = tid & 31;
    int wid  = tid >> 5;
    int wm   = wid & 1;                     // 64-row half
    int wn   = wid >> 1;                    // 32-col quarter

    int lrow[2], lcol[2];
#pragma unroll
    for (int i = 0; i < 2; i++) {
        int c = tid + 256 * i;
        lrow[i] = c >> 2;                   // 0..127
        lcol[i] = (c & 3) * 8;              // 0,8,16,24
    }

    const __half* Bsrc = g_W1h + (size_t)(nblk * 128) * 256;

    auto issue_tile = [&](int kt) {
        int s = kt & 1;
        int kb = kt * 32;
#pragma unroll
        for (int i = 0; i < 2; i++) {
            {
                unsigned dst = smem_u32(&As[s][lrow[i] * PADK + lcol[i]]);
                const __half* src = g_Ah + (size_t)(row0 + lrow[i]) * HID + kb + lcol[i];
                int sz = (row0 + lrow[i] < M) ? 16 : 0;
                asm volatile("cp.async.cg.shared.global [%0], [%1], 16, %2;\n"
                             :: "r"(dst), "l"(src), "r"(sz));
            }
            {
                unsigned dst = smem_u32(&Bs[s][lrow[i] * PADK + lcol[i]]);
                const __half* src = Bsrc + (size_t)lrow[i] * 256 + kb + lcol[i];
                asm volatile("cp.async.cg.shared.global [%0], [%1], 16;\n"
                             :: "r"(dst), "l"(src));
            }
        }
        asm volatile("cp.async.commit_group;\n");
    };

    float acc[4][4][4];
#pragma unroll
    for (int i = 0; i < 4; i++)
#pragma unroll
        for (int j = 0; j < 4; j++)
#pragma unroll
            for (int r = 0; r < 4; r++) acc[i][j][r] = 0.0f;

    issue_tile(0);

    for (int kt = 0; kt < 8; kt++) {
        if (kt < 7) {
            issue_tile(kt + 1);
            asm volatile("cp.async.wait_group 1;\n");
        } else {
            asm volatile("cp.async.wait_group 0;\n");
        }
        __syncthreads();

        int s = kt & 1;
        const __half* Asb = &As[s][wm * 64 * PADK];
        const __half* Bsb = &Bs[s][wn * 32 * PADK];

#pragma unroll
        for (int ks = 0; ks < 2; ks++) {
            int kb = ks * 16;
            unsigned af[4][4];
            unsigned bf[4][2];
#pragma unroll
            for (int mt = 0; mt < 4; mt++) {
                unsigned addr = smem_u32(Asb + (mt * 16 + (lane & 15)) * PADK + kb + (lane >> 4) * 8);
                asm volatile("ldmatrix.sync.aligned.m8n8.x4.shared.b16 {%0,%1,%2,%3}, [%4];\n"
                             : "=r"(af[mt][0]), "=r"(af[mt][1]), "=r"(af[mt][2]), "=r"(af[mt][3])
                             : "r"(addr));
            }
#pragma unroll
            for (int nt = 0; nt < 4; nt++) {
                unsigned addr = smem_u32(Bsb + (nt * 8 + (lane & 7)) * PADK + kb + ((lane >> 3) & 1) * 8);
                asm volatile("ldmatrix.sync.aligned.m8n8.x2.shared.b16 {%0,%1}, [%2];\n"
                             : "=r"(bf[nt][0]), "=r"(bf[nt][1])
                             : "r"(addr));
            }
#pragma unroll
            for (int mt = 0; mt < 4; mt++)
#pragma unroll
                for (int nt = 0; nt < 4; nt++) {
                    asm volatile(
                        "mma.sync.aligned.m16n8k16.row.col.f32.f16.f16.f32 "
                        "{%0,%1,%2,%3}, {%4,%5,%6,%7}, {%8,%9}, {%0,%1,%2,%3};\n"
                        : "+f"(acc[mt][nt][0]), "+f"(acc[mt][nt][1]),
                          "+f"(acc[mt][nt][2]), "+f"(acc[mt][nt][3])
                        : "r"(af[mt][0]), "r"(af[mt][1]), "r"(af[mt][2]), "r"(af[mt][3]),
                          "r"(bf[nt][0]), "r"(bf[nt][1]));
                }
        }
        __syncthreads();
    }

    // epilogue: add b1 to P1 columns (nblk 0,1), fp16 store
    int gcol_base = nblk * 128 + wn * 32 + (lane & 3) * 2;
    int grow_base = row0 + wm * 64 + (lane >> 2);
#pragma unroll
    for (int mt = 0; mt < 4; mt++) {
#pragma unroll
        for (int nt = 0; nt < 4; nt++) {
            int gc = gcol_base + nt * 8;
            float add0 = 0.0f, add1 = 0.0f;
            if (nblk < 2) { add0 = b1[gc]; add1 = b1[gc + 1]; }
            int r0 = grow_base + mt * 16;
            if (r0 < M)
                *(__half2*)(g_Ph + (size_t)r0 * 512 + gc) =
                    __floats2half2_rn(acc[mt][nt][0] + add0, acc[mt][nt][1] + add1);
            if (r0 + 8 < M)
                *(__half2*)(g_Ph + (size_t)(r0 + 8) * 512 + gc) =
                    __floats2half2_rn(acc[mt][nt][2] + add0, acc[mt][nt][3] + add1);
        }
    }
}

// ---------------------------------------------------------------------------
__device__ __forceinline__ void atomicMaxF(float* a, float v) {
    if (v >= 0.0f) atomicMax((int*)a, __float_as_int(v));
    else           atomicMin((unsigned int*)a, __float_as_uint(v));
}

// ---------------------------------------------------------------------------
// gather: warp per move. 3 x 16B loads per warp (P1 row, P2 row, W2 fp16).
// ---------------------------------------------------------------------------
__global__ __launch_bounds__(256) void gather_logits_kernel(
    const void* __restrict__ moves,
    const void* __restrict__ batch,
    const float* __restrict__ b2,
    int NM)
{
    int warp = (blockIdx.x * blockDim.x + threadIdx.x) >> 5;
    int lane = threadIdx.x & 31;
    if (warp >= NM) return;

    int is64 = g_is64;
    long long s = load_idx(moves, warp, is64);
    long long t = load_idx(moves, (size_t)NM + warp, is64);

    uint4 u1 = ((const uint4*)(g_Ph + (size_t)s * 512))[lane];
    uint4 u2 = ((const uint4*)(g_Ph + (size_t)t * 512 + 256))[lane];
    uint4 uw = ((const uint4*)g_W2h)[lane];

    float2 a0 = __half22float2(*(const __half2*)&u1.x);
    float2 a1 = __half22float2(*(const __half2*)&u1.y);
    float2 a2 = __half22float2(*(const __half2*)&u1.z);
    float2 a3 = __half22float2(*(const __half2*)&u1.w);
    float2 d0 = __half22float2(*(const __half2*)&u2.x);
    float2 d1 = __half22float2(*(const __half2*)&u2.y);
    float2 d2 = __half22float2(*(const __half2*)&u2.z);
    float2 d3 = __half22float2(*(const __half2*)&u2.w);
    float2 w0 = __half22float2(*(const __half2*)&uw.x);
    float2 w1 = __half22float2(*(const __half2*)&uw.y);
    float2 w2 = __half22float2(*(const __half2*)&uw.z);
    float2 w3 = __half22float2(*(const __half2*)&uw.w);

    float acc = 0.0f;
    acc += fmaxf(a0.x + d0.x, 0.0f) * w0.x;
    acc += fmaxf(a0.y + d0.y, 0.0f) * w0.y;
    acc += fmaxf(a1.x + d1.x, 0.0f) * w1.x;
    acc += fmaxf(a1.y + d1.y, 0.0f) * w1.y;
    acc += fmaxf(a2.x + d2.x, 0.0f) * w2.x;
    acc += fmaxf(a2.y + d2.y, 0.0f) * w2.y;
    acc += fmaxf(a3.x + d3.x, 0.0f) * w3.x;
    acc += fmaxf(a3.y + d3.y, 0.0f) * w3.y;

#pragma unroll
    for (int o = 16; o; o >>= 1) acc += __shfl_xor_sync(0xffffffffu, acc, o);

    if (lane == 0) {
        float logit = acc + b2[0];
        int g = (int)load_idx(batch, (size_t)s, is64);
        g_logits[warp] = logit;
        g_mb[warp] = g;
        atomicMaxF(&g_segmax[g], logit);
    }
}

// ---------------------------------------------------------------------------
__global__ void exp_kernel(int NM) {
    int i = blockIdx.x * blockDim.x + threadIdx.x;
    if (i < NM) {
        int g = g_mb[i];
        atomicAdd(&g_segsum[g], expf(g_logits[i] - g_segmax[g]));
    }
}

__global__ void div_kernel(float* __restrict__ out, int NM) {
    int i = blockIdx.x * blockDim.x + threadIdx.x;
    if (i < NM) {
        int g = g_mb[i];
        float e = expf(g_logits[i] - g_segmax[g]);
        out[i] = e / (g_segsum[g] + 1e-16f);
    }
}

// ---------------------------------------------------------------------------
extern "C" void kernel_launch(void* const* d_in, const int* in_sizes, int n_in,
                              void* d_out, int out_size)
{
    const float* emb   = (const float*)d_in[0];
    const void*  moves = d_in[1];
    const void*  batch = d_in[2];
    const float* W1    = (const float*)d_in[3];
    const float* b1    = (const float*)d_in[4];
    const float* W2    = (const float*)d_in[5];
    const float* b2    = (const float*)d_in[6];

    int M  = in_sizes[0] / HID;   // 100000
    int NM = in_sizes[1] / 2;     // 500000

    detect_dtype_kernel<<<1, 1>>>((const int*)moves);
    init_seg_kernel<<<1, NG>>>();

    int n4 = M * HID / 4;
    convert_A_kernel<<<(n4 + 255) / 256, 256>>>(emb, n4);
    convert_W1_kernel<<<(512 * 256 + 255) / 256, 256>>>(W1, W2);

    dim3 ggrid(4, (M + 127) / 128);
    hgemm_kernel<<<ggrid, 256>>>(b1, M);

    int gblocks = (NM + 7) / 8;
    gather_logits_kernel<<<gblocks, 256>>>(moves, batch, b2, NM);

    exp_kernel<<<(NM + 255) / 256, 256>>>(NM);
    div_kernel<<<(NM + 255) / 256, 256>>>((float*)d_out, NM);
}

// round 10
// speedup vs baseline: 2.6769x; 1.0337x over previous
#include <cuda_runtime.h>
#include <cuda_fp16.h>

#define HID  256
#define NG   512
#define MAXN 100000
#define MAXE 500000
#define PADK 40            // B smem row stride (fp16): 32 data + 8 pad
#define PADA 264           // A smem row stride (fp16): 256 data + 8 pad

// Scratch (device globals)
__device__ __half g_Ah[(size_t)MAXN * HID];    // emb in fp16
__device__ __half g_W1h[512 * 256];            // W1 transposed: [(h*256+n)][k]
__device__ __half g_W2h[256];                  // W2 in fp16
__device__ __half g_Ph[(size_t)MAXN * 512];    // P: cols 0..255 = P1+b1, 256..511 = P2
__device__ float  g_logits[MAXE];
__device__ int    g_mb[MAXE];
__device__ float  g_segmax[NG];
__device__ float  g_segsum[NG];
__device__ int    g_is64;

// ---------------------------------------------------------------------------
__global__ void detect_dtype_kernel(const int* __restrict__ moves_i32) {
    int acc = 0;
#pragma unroll 8
    for (int i = 1; i < 2048; i += 2) acc |= moves_i32[i];
    g_is64 = (acc == 0) ? 1 : 0;
}

__device__ __forceinline__ long long load_idx(const void* p, size_t i, int is64) {
    if (is64) return ((const long long*)p)[i];
    return (long long)((const int*)p)[i];
}

__global__ void init_seg_kernel() {
    int i = threadIdx.x;
    if (i < NG) {
        g_segmax[i] = __int_as_float(0xff800000);
        g_segsum[i] = 0.0f;
    }
}

// ---------------------------------------------------------------------------
// converts: emb -> fp16 (8 elems/thread, 16B store), W1 -> [n][k] fp16, W2 fp16
// ---------------------------------------------------------------------------
__global__ void convert_A_kernel(const float* __restrict__ A, int n8) {
    int i = blockIdx.x * blockDim.x + threadIdx.x;
    if (i < n8) {
        const float4* src = (const float4*)A + (size_t)i * 2;
        float4 v0 = src[0];
        float4 v1 = src[1];
        __half2 h[4];
        h[0] = __floats2half2_rn(v0.x, v0.y);
        h[1] = __floats2half2_rn(v0.z, v0.w);
        h[2] = __floats2half2_rn(v1.x, v1.y);
        h[3] = __floats2half2_rn(v1.z, v1.w);
        *((uint4*)g_Ah + i) = *(const uint4*)h;
    }
}

__global__ void convert_W1_kernel(const float* __restrict__ W1,
                                  const float* __restrict__ W2) {
    int e = blockIdx.x * blockDim.x + threadIdx.x;   // 0 .. 512*256-1
    if (e < 512 * 256) {
        int r = e >> 8;          // W1 row (feature index) 0..511
        int n = e & 255;         // W1 col (output j)
        int h = r >> 8;          // half 0/1
        int k = r & 255;         // k within half
        g_W1h[(h * 256 + n) * 256 + k] = __float2half(W1[e]);
    }
    if (e < 256) g_W2h[e] = __float2half(W2[e]);
}

// ---------------------------------------------------------------------------
// fp16 GEMM with A-stripe reuse: P[M, 512] = Ah[M,256] @ W1h^T (+b1 cols 0..255)
//   One CTA per 128-row stripe. Whole A stripe (128x256) resident in smem;
//   B streamed as 32 double-buffered 128x32 tiles (4 nblk x 8 kt).
//   256 threads / 8 warps, warp tile 64x32, m16n8k16, ldmatrix.
// ---------------------------------------------------------------------------
__device__ __forceinline__ unsigned smem_u32(const void* p) {
    return (unsigned)__cvta_generic_to_shared(p);
}

__global__ __launch_bounds__(256) void hgemm_kernel(const float* __restrict__ b1, int M) {
    extern __shared__ __half sm[];
    __half* As = sm;                        // 128 x PADA
    __half* Bs = sm + 128 * PADA;           // 2 x 128 x PADK

    int row0 = blockIdx.x * 128;
    int tid  = threadIdx.x;
    int lane = tid & 31;
    int wid  = tid >> 5;
    int wm   = wid & 1;                     // 64-row half
    int wn   = wid >> 1;                    // 32-col quarter

    // ---- issue A stripe: 128 rows x 256 halves = 4096 16B-chunks, 16/thread
    {
#pragma unroll
        for (int i = 0; i < 16; i++) {
            int c = i * 256 + tid;          // 0..4095
            int r = c >> 5;                 // 0..127
            int col = (c & 31) * 8;         // 0..248
            unsigned dst = smem_u32(As + r * PADA + col);
            const __half* src = g_Ah + (size_t)(row0 + r) * HID + col;
            int sz = (row0 + r < M) ? 16 : 0;
            asm volatile("cp.async.cg.shared.global [%0], [%1], 16, %2;\n"
                         :: "r"(dst), "l"(src), "r"(sz));
        }
        asm volatile("cp.async.commit_group;\n");
    }

    // ---- B tile issue: tile t -> nblk = t>>3, kt = t&7; 512 chunks, 2/thread
    auto issue_B = [&](int t) {
        int s  = t & 1;
        int nb = t >> 3;
        int kt = t & 7;
#pragma unroll
        for (int i = 0; i < 2; i++) {
            int c = i * 256 + tid;          // 0..511
            int r = c >> 2;                 // 0..127
            int col = (c & 3) * 8;          // 0,8,16,24
            unsigned dst = smem_u32(Bs + s * 128 * PADK + r * PADK + col);
            const __half* src = g_W1h + (size_t)(nb * 128 + r) * 256 + kt * 32 + col;
            asm volatile("cp.async.cg.shared.global [%0], [%1], 16;\n"
                         :: "r"(dst), "l"(src));
        }
        asm volatile("cp.async.commit_group;\n");
    };

    issue_B(0);

    float acc[4][4][4];
#pragma unroll
    for (int i = 0; i < 4; i++)
#pragma unroll
        for (int j = 0; j < 4; j++)
#pragma unroll
            for (int r = 0; r < 4; r++) acc[i][j][r] = 0.0f;

    for (int t = 0; t < 32; t++) {
        if (t < 31) {
            issue_B(t + 1);
            asm volatile("cp.async.wait_group 1;\n");   // A + B_t complete
        } else {
            asm volatile("cp.async.wait_group 0;\n");
        }
        __syncthreads();

        int s = t & 1;
        const __half* Asb = As + wm * 64 * PADA;
        const __half* Bsb = Bs + s * 128 * PADK + wn * 32 * PADK;
        int kt = t & 7;

#pragma unroll
        for (int ks = 0; ks < 2; ks++) {
            int ka = kt * 32 + ks * 16;     // A column offset
            int kb = ks * 16;               // B tile column offset
            unsigned af[4][4];
            unsigned bf[4][2];
#pragma unroll
            for (int mt = 0; mt < 4; mt++) {
                unsigned addr = smem_u32(Asb + (mt * 16 + (lane & 15)) * PADA + ka + (lane >> 4) * 8);
                asm volatile("ldmatrix.sync.aligned.m8n8.x4.shared.b16 {%0,%1,%2,%3}, [%4];\n"
                             : "=r"(af[mt][0]), "=r"(af[mt][1]), "=r"(af[mt][2]), "=r"(af[mt][3])
                             : "r"(addr));
            }
#pragma unroll
            for (int nt = 0; nt < 4; nt++) {
                unsigned addr = smem_u32(Bsb + (nt * 8 + (lane & 7)) * PADK + kb + ((lane >> 3) & 1) * 8);
                asm volatile("ldmatrix.sync.aligned.m8n8.x2.shared.b16 {%0,%1}, [%2];\n"
                             : "=r"(bf[nt][0]), "=r"(bf[nt][1])
                             : "r"(addr));
            }
#pragma unroll
            for (int mt = 0; mt < 4; mt++)
#pragma unroll
                for (int nt = 0; nt < 4; nt++) {
                    asm volatile(
                        "mma.sync.aligned.m16n8k16.row.col.f32.f16.f16.f32 "
                        "{%0,%1,%2,%3}, {%4,%5,%6,%7}, {%8,%9}, {%0,%1,%2,%3};\n"
                        : "+f"(acc[mt][nt][0]), "+f"(acc[mt][nt][1]),
                          "+f"(acc[mt][nt][2]), "+f"(acc[mt][nt][3])
                        : "r"(af[mt][0]), "r"(af[mt][1]), "r"(af[mt][2]), "r"(af[mt][3]),
                          "r"(bf[nt][0]), "r"(bf[nt][1]));
                }
        }
        __syncthreads();

        if (kt == 7) {
            // epilogue for this nblk, then reset acc
            int nblk = t >> 3;
            int gcol_base = nblk * 128 + wn * 32 + (lane & 3) * 2;
            int grow_base = row0 + wm * 64 + (lane >> 2);
#pragma unroll
            for (int mt = 0; mt < 4; mt++) {
#pragma unroll
                for (int nt = 0; nt < 4; nt++) {
                    int gc = gcol_base + nt * 8;
                    float add0 = 0.0f, add1 = 0.0f;
                    if (nblk < 2) { add0 = b1[gc]; add1 = b1[gc + 1]; }
                    int r0 = grow_base + mt * 16;
                    if (r0 < M)
                        *(__half2*)(g_Ph + (size_t)r0 * 512 + gc) =
                            __floats2half2_rn(acc[mt][nt][0] + add0, acc[mt][nt][1] + add1);
                    if (r0 + 8 < M)
                        *(__half2*)(g_Ph + (size_t)(r0 + 8) * 512 + gc) =
                            __floats2half2_rn(acc[mt][nt][2] + add0, acc[mt][nt][3] + add1);
#pragma unroll
                    for (int r = 0; r < 4; r++) acc[mt][nt][r] = 0.0f;
                }
            }
        }
    }
}

// ---------------------------------------------------------------------------
__device__ __forceinline__ void atomicMaxF(float* a, float v) {
    if (v >= 0.0f) atomicMax((int*)a, __float_as_int(v));
    else           atomicMin((unsigned int*)a, __float_as_uint(v));
}

// ---------------------------------------------------------------------------
// gather: warp per move. 3 x 16B loads per warp (P1 row, P2 row, W2 fp16).
// ---------------------------------------------------------------------------
__global__ __launch_bounds__(256) void gather_logits_kernel(
    const void* __restrict__ moves,
    const void* __restrict__ batch,
    const float* __restrict__ b2,
    int NM)
{
    int warp = (blockIdx.x * blockDim.x + threadIdx.x) >> 5;
    int lane = threadIdx.x & 31;
    if (warp >= NM) return;

    int is64 = g_is64;
    long long s = load_idx(moves, warp, is64);
    long long t = load_idx(moves, (size_t)NM + warp, is64);

    uint4 u1 = ((const uint4*)(g_Ph + (size_t)s * 512))[lane];
    uint4 u2 = ((const uint4*)(g_Ph + (size_t)t * 512 + 256))[lane];
    uint4 uw = ((const uint4*)g_W2h)[lane];

    float2 a0 = __half22float2(*(const __half2*)&u1.x);
    float2 a1 = __half22float2(*(const __half2*)&u1.y);
    float2 a2 = __half22float2(*(const __half2*)&u1.z);
    float2 a3 = __half22float2(*(const __half2*)&u1.w);
    float2 d0 = __half22float2(*(const __half2*)&u2.x);
    float2 d1 = __half22float2(*(const __half2*)&u2.y);
    float2 d2 = __half22float2(*(const __half2*)&u2.z);
    float2 d3 = __half22float2(*(const __half2*)&u2.w);
    float2 w0 = __half22float2(*(const __half2*)&uw.x);
    float2 w1 = __half22float2(*(const __half2*)&uw.y);
    float2 w2 = __half22float2(*(const __half2*)&uw.z);
    float2 w3 = __half22float2(*(const __half2*)&uw.w);

    float acc = 0.0f;
    acc += fmaxf(a0.x + d0.x, 0.0f) * w0.x;
    acc += fmaxf(a0.y + d0.y, 0.0f) * w0.y;
    acc += fmaxf(a1.x + d1.x, 0.0f) * w1.x;
    acc += fmaxf(a1.y + d1.y, 0.0f) * w1.y;
    acc += fmaxf(a2.x + d2.x, 0.0f) * w2.x;
    acc += fmaxf(a2.y + d2.y, 0.0f) * w2.y;
    acc += fmaxf(a3.x + d3.x, 0.0f) * w3.x;
    acc += fmaxf(a3.y + d3.y, 0.0f) * w3.y;

#pragma unroll
    for (int o = 16; o; o >>= 1) acc += __shfl_xor_sync(0xffffffffu, acc, o);

    if (lane == 0) {
        float logit = acc + b2[0];
        int g = (int)load_idx(batch, (size_t)s, is64);
        g_logits[warp] = logit;
        g_mb[warp] = g;
        atomicMaxF(&g_segmax[g], logit);
    }
}

// ---------------------------------------------------------------------------
// softmax tail, 4 moves per thread
// ---------------------------------------------------------------------------
__global__ void exp_kernel(int NM) {
    int i = blockIdx.x * blockDim.x + threadIdx.x;
    int base = i * 4;
    if (base + 3 < NM) {
        float4 l = *(const float4*)(g_logits + base);
        int4   g = *(const int4*)(g_mb + base);
        atomicAdd(&g_segsum[g.x], expf(l.x - g_segmax[g.x]));
        atomicAdd(&g_segsum[g.y], expf(l.y - g_segmax[g.y]));
        atomicAdd(&g_segsum[g.z], expf(l.z - g_segmax[g.z]));
        atomicAdd(&g_segsum[g.w], expf(l.w - g_segmax[g.w]));
    } else {
        for (int k = base; k < NM; k++) {
            int g = g_mb[k];
            atomicAdd(&g_segsum[g], expf(g_logits[k] - g_segmax[g]));
        }
    }
}

__global__ void div_kernel(float* __restrict__ out, int NM) {
    int i = blockIdx.x * blockDim.x + threadIdx.x;
    int base = i * 4;
    if (base + 3 < NM) {
        float4 l = *(const float4*)(g_logits + base);
        int4   g = *(const int4*)(g_mb + base);
        float4 r;
        r.x = expf(l.x - g_segmax[g.x]) / (g_segsum[g.x] + 1e-16f);
        r.y = expf(l.y - g_segmax[g.y]) / (g_segsum[g.y] + 1e-16f);
        r.z = expf(l.z - g_segmax[g.z]) / (g_segsum[g.z] + 1e-16f);
        r.w = expf(l.w - g_segmax[g.w]) / (g_segsum[g.w] + 1e-16f);
        *(float4*)(out + base) = r;
    } else {
        for (int k = base; k < NM; k++) {
            int g = g_mb[k];
            out[k] = expf(g_logits[k] - g_segmax[g]) / (g_segsum[g] + 1e-16f);
        }
    }
}

// ---------------------------------------------------------------------------
extern "C" void kernel_launch(void* const* d_in, const int* in_sizes, int n_in,
                              void* d_out, int out_size)
{
    const float* emb   = (const float*)d_in[0];
    const void*  moves = d_in[1];
    const void*  batch = d_in[2];
    const float* W1    = (const float*)d_in[3];
    const float* b1    = (const float*)d_in[4];
    const float* W2    = (const float*)d_in[5];
    const float* b2    = (const float*)d_in[6];

    int M  = in_sizes[0] / HID;   // 100000
    int NM = in_sizes[1] / 2;     // 500000

    detect_dtype_kernel<<<1, 1>>>((const int*)moves);
    init_seg_kernel<<<1, NG>>>();

    int n8 = M * HID / 8;
    convert_A_kernel<<<(n8 + 255) / 256, 256>>>(emb, n8);
    convert_W1_kernel<<<(512 * 256 + 255) / 256, 256>>>(W1, W2);

    const int smem_bytes = (128 * PADA + 2 * 128 * PADK) * 2;   // 88064 B
    cudaFuncSetAttribute(hgemm_kernel, cudaFuncAttributeMaxDynamicSharedMemorySize, smem_bytes);
    hgemm_kernel<<<(M + 127) / 128, 256, smem_bytes>>>(b1, M);

    int gblocks = (NM + 7) / 8;
    gather_logits_kernel<<<gblocks, 256>>>(moves, batch, b2, NM);

    int q = (NM + 3) / 4;
    exp_kernel<<<(q + 255) / 256, 256>>>(NM);
    div_kernel<<<(q + 255) / 256, 256>>>((float*)d_out, NM);
}

// round 11
// speedup vs baseline: 3.3301x; 1.2440x over previous
#include <cuda_runtime.h>
#include <cuda_fp16.h>

#define HID  256
#define NG   512
#define MAXN 100000
#define MAXE 500000
#define PADK 40            // B smem row stride (fp16): 32 data + 8 pad
#define PADA 264           // A smem row stride (fp16): 256 data + 8 pad

// Scratch (device globals)
__device__ __half g_Ah[(size_t)MAXN * HID];    // emb in fp16
__device__ __half g_W1h[512 * 256];            // W1 transposed: [(h*256+n)][k]
__device__ __half g_W2h[256];                  // W2 in fp16
__device__ __half g_Ph[(size_t)MAXN * 512];    // P: cols 0..255 = P1+b1, 256..511 = P2
__device__ float  g_e[MAXE];                   // exp(logit)
__device__ int    g_mb[MAXE];
__device__ float  g_segsum[NG];
__device__ int    g_is64;

// ---------------------------------------------------------------------------
// init: zero segsum; thread 0 also detects index dtype
// (int64 => all odd 32-bit words zero for values < 2^31)
// ---------------------------------------------------------------------------
__global__ void init_kernel(const int* __restrict__ moves_i32) {
    int i = threadIdx.x;
    if (i < NG) g_segsum[i] = 0.0f;
    if (i == 0) {
        int acc = 0;
#pragma unroll 8
        for (int k = 1; k < 2048; k += 2) acc |= moves_i32[k];
        g_is64 = (acc == 0) ? 1 : 0;
    }
}

__device__ __forceinline__ long long load_idx(const void* p, size_t i, int is64) {
    if (is64) return ((const long long*)p)[i];
    return (long long)((const int*)p)[i];
}

// ---------------------------------------------------------------------------
// converts: emb -> fp16 (8 elems/thread, 16B store), W1 -> [n][k] fp16, W2 fp16
// ---------------------------------------------------------------------------
__global__ void convert_A_kernel(const float* __restrict__ A, int n8) {
    int i = blockIdx.x * blockDim.x + threadIdx.x;
    if (i < n8) {
        const float4* src = (const float4*)A + (size_t)i * 2;
        float4 v0 = src[0];
        float4 v1 = src[1];
        __half2 h[4];
        h[0] = __floats2half2_rn(v0.x, v0.y);
        h[1] = __floats2half2_rn(v0.z, v0.w);
        h[2] = __floats2half2_rn(v1.x, v1.y);
        h[3] = __floats2half2_rn(v1.z, v1.w);
        *((uint4*)g_Ah + i) = *(const uint4*)h;
    }
}

__global__ void convert_W1_kernel(const float* __restrict__ W1,
                                  const float* __restrict__ W2) {
    int e = blockIdx.x * blockDim.x + threadIdx.x;   // 0 .. 512*256-1
    if (e < 512 * 256) {
        int r = e >> 8;          // W1 row (feature index) 0..511
        int n = e & 255;         // W1 col (output j)
        int h = r >> 8;          // half 0/1
        int k = r & 255;         // k within half
        g_W1h[(h * 256 + n) * 256 + k] = __float2half(W1[e]);
    }
    if (e < 256) g_W2h[e] = __float2half(W2[e]);
}

// ---------------------------------------------------------------------------
// fp16 GEMM with A-stripe reuse: P[M, 512] = Ah[M,256] @ W1h^T (+b1 cols 0..255)
//   One CTA per 128-row stripe; A stripe resident, B double-buffered.
// ---------------------------------------------------------------------------
__device__ __forceinline__ unsigned smem_u32(const void* p) {
    return (unsigned)__cvta_generic_to_shared(p);
}

__global__ __launch_bounds__(256) void hgemm_kernel(const float* __restrict__ b1, int M) {
    extern __shared__ __half sm[];
    __half* As = sm;                        // 128 x PADA
    __half* Bs = sm + 128 * PADA;           // 2 x 128 x PADK

    int row0 = blockIdx.x * 128;
    int tid  = threadIdx.x;
    int lane = tid & 31;
    int wid  = tid >> 5;
    int wm   = wid & 1;                     // 64-row half
    int wn   = wid >> 1;                    // 32-col quarter

    {
#pragma unroll
        for (int i = 0; i < 16; i++) {
            int c = i * 256 + tid;          // 0..4095
            int r = c >> 5;                 // 0..127
            int col = (c & 31) * 8;         // 0..248
            unsigned dst = smem_u32(As + r * PADA + col);
            const __half* src = g_Ah + (size_t)(row0 + r) * HID + col;
            int sz = (row0 + r < M) ? 16 : 0;
            asm volatile("cp.async.cg.shared.global [%0], [%1], 16, %2;\n"
                         :: "r"(dst), "l"(src), "r"(sz));
        }
        asm volatile("cp.async.commit_group;\n");
    }

    auto issue_B = [&](int t) {
        int s  = t & 1;
        int nb = t >> 3;
        int kt = t & 7;
#pragma unroll
        for (int i = 0; i < 2; i++) {
            int c = i * 256 + tid;          // 0..511
            int r = c >> 2;                 // 0..127
            int col = (c & 3) * 8;          // 0,8,16,24
            unsigned dst = smem_u32(Bs + s * 128 * PADK + r * PADK + col);
            const __half* src = g_W1h + (size_t)(nb * 128 + r) * 256 + kt * 32 + col;
            asm volatile("cp.async.cg.shared.global [%0], [%1], 16;\n"
                         :: "r"(dst), "l"(src));
        }
        asm volatile("cp.async.commit_group;\n");
    };

    issue_B(0);

    float acc[4][4][4];
#pragma unroll
    for (int i = 0; i < 4; i++)
#pragma unroll
        for (int j = 0; j < 4; j++)
#pragma unroll
            for (int r = 0; r < 4; r++) acc[i][j][r] = 0.0f;

    for (int t = 0; t < 32; t++) {
        if (t < 31) {
            issue_B(t + 1);
            asm volatile("cp.async.wait_group 1;\n");
        } else {
            asm volatile("cp.async.wait_group 0;\n");
        }
        __syncthreads();

        int s = t & 1;
        const __half* Asb = As + wm * 64 * PADA;
        const __half* Bsb = Bs + s * 128 * PADK + wn * 32 * PADK;
        int kt = t & 7;

#pragma unroll
        for (int ks = 0; ks < 2; ks++) {
            int ka = kt * 32 + ks * 16;
            int kb = ks * 16;
            unsigned af[4][4];
            unsigned bf[4][2];
#pragma unroll
            for (int mt = 0; mt < 4; mt++) {
                unsigned addr = smem_u32(Asb + (mt * 16 + (lane & 15)) * PADA + ka + (lane >> 4) * 8);
                asm volatile("ldmatrix.sync.aligned.m8n8.x4.shared.b16 {%0,%1,%2,%3}, [%4];\n"
                             : "=r"(af[mt][0]), "=r"(af[mt][1]), "=r"(af[mt][2]), "=r"(af[mt][3])
                             : "r"(addr));
            }
#pragma unroll
            for (int nt = 0; nt < 4; nt++) {
                unsigned addr = smem_u32(Bsb + (nt * 8 + (lane & 7)) * PADK + kb + ((lane >> 3) & 1) * 8);
                asm volatile("ldmatrix.sync.aligned.m8n8.x2.shared.b16 {%0,%1}, [%2];\n"
                             : "=r"(bf[nt][0]), "=r"(bf[nt][1])
                             : "r"(addr));
            }
#pragma unroll
            for (int mt = 0; mt < 4; mt++)
#pragma unroll
                for (int nt = 0; nt < 4; nt++) {
                    asm volatile(
                        "mma.sync.aligned.m16n8k16.row.col.f32.f16.f16.f32 "
                        "{%0,%1,%2,%3}, {%4,%5,%6,%7}, {%8,%9}, {%0,%1,%2,%3};\n"
                        : "+f"(acc[mt][nt][0]), "+f"(acc[mt][nt][1]),
                          "+f"(acc[mt][nt][2]), "+f"(acc[mt][nt][3])
                        : "r"(af[mt][0]), "r"(af[mt][1]), "r"(af[mt][2]), "r"(af[mt][3]),
                          "r"(bf[nt][0]), "r"(bf[nt][1]));
                }
        }
        __syncthreads();

        if (kt == 7) {
            int nblk = t >> 3;
            int gcol_base = nblk * 128 + wn * 32 + (lane & 3) * 2;
            int grow_base = row0 + wm * 64 + (lane >> 2);
#pragma unroll
            for (int mt = 0; mt < 4; mt++) {
#pragma unroll
                for (int nt = 0; nt < 4; nt++) {
                    int gc = gcol_base + nt * 8;
                    float add0 = 0.0f, add1 = 0.0f;
                    if (nblk < 2) { add0 = b1[gc]; add1 = b1[gc + 1]; }
                    int r0 = grow_base + mt * 16;
                    if (r0 < M)
                        *(__half2*)(g_Ph + (size_t)r0 * 512 + gc) =
                            __floats2half2_rn(acc[mt][nt][0] + add0, acc[mt][nt][1] + add1);
                    if (r0 + 8 < M)
                        *(__half2*)(g_Ph + (size_t)(r0 + 8) * 512 + gc) =
                            __floats2half2_rn(acc[mt][nt][2] + add0, acc[mt][nt][3] + add1);
#pragma unroll
                    for (int r = 0; r < 4; r++) acc[mt][nt][r] = 0.0f;
                }
            }
        }
    }
}

// ---------------------------------------------------------------------------
// gather: 8 lanes per move, 4 moves per warp (MLP=8 independent P loads/lane).
// No max pass: e = exp(logit) accumulated straight into segsum.
// ---------------------------------------------------------------------------
__global__ __launch_bounds__(256) void gather_logits_kernel(
    const void* __restrict__ moves,
    const void* __restrict__ batch,
    const float* __restrict__ b2,
    int NM)
{
    int warp = (blockIdx.x * blockDim.x + threadIdx.x) >> 5;
    int lane = threadIdx.x & 31;
    int grp  = lane >> 3;                   // 0..3
    int q    = lane & 7;                    // 0..7
    int m    = warp * 4 + grp;
    if (m >= NM) return;

    int is64 = g_is64;
    long long s = load_idx(moves, m, is64);
    long long t = load_idx(moves, (size_t)NM + m, is64);

    const uint4* p1 = (const uint4*)(g_Ph + (size_t)s * 512);        // 32 uint4
    const uint4* p2 = (const uint4*)(g_Ph + (size_t)t * 512 + 256);
    const uint4* pw = (const uint4*)g_W2h;

    // issue all 8 P loads (independent addresses) before consuming
    uint4 u1[4], u2[4], uw[4];
#pragma unroll
    for (int i = 0; i < 4; i++) {
        u1[i] = p1[q + 8 * i];
        u2[i] = p2[q + 8 * i];
        uw[i] = pw[q + 8 * i];
    }

    float acc = 0.0f;
#pragma unroll
    for (int i = 0; i < 4; i++) {
        const __half2* a = (const __half2*)&u1[i];
        const __half2* d = (const __half2*)&u2[i];
        const __half2* w = (const __half2*)&uw[i];
#pragma unroll
        for (int j = 0; j < 4; j++) {
            float2 av = __half22float2(a[j]);
            float2 dv = __half22float2(d[j]);
            float2 wv = __half22float2(w[j]);
            acc += fmaxf(av.x + dv.x, 0.0f) * wv.x;
            acc += fmaxf(av.y + dv.y, 0.0f) * wv.y;
        }
    }

    // reduce within the 8-lane group
    acc += __shfl_xor_sync(0xffffffffu, acc, 4);
    acc += __shfl_xor_sync(0xffffffffu, acc, 2);
    acc += __shfl_xor_sync(0xffffffffu, acc, 1);

    if (q == 0) {
        float e = expf(acc + b2[0]);
        int g = (int)load_idx(batch, (size_t)s, is64);
        g_e[m] = e;
        g_mb[m] = g;
        atomicAdd(&g_segsum[g], e);
    }
}

// ---------------------------------------------------------------------------
// div: probs = e / (segsum + eps), 4 per thread
// ---------------------------------------------------------------------------
__global__ void div_kernel(float* __restrict__ out, int NM) {
    int i = blockIdx.x * blockDim.x + threadIdx.x;
    int base = i * 4;
    if (base + 3 < NM) {
        float4 e = *(const float4*)(g_e + base);
        int4   g = *(const int4*)(g_mb + base);
        float4 r;
        r.x = e.x / (g_segsum[g.x] + 1e-16f);
        r.y = e.y / (g_segsum[g.y] + 1e-16f);
        r.z = e.z / (g_segsum[g.z] + 1e-16f);
        r.w = e.w / (g_segsum[g.w] + 1e-16f);
        *(float4*)(out + base) = r;
    } else {
        for (int k = base; k < NM; k++)
            out[k] = g_e[k] / (g_segsum[g_mb[k]] + 1e-16f);
    }
}

// ---------------------------------------------------------------------------
extern "C" void kernel_launch(void* const* d_in, const int* in_sizes, int n_in,
                              void* d_out, int out_size)
{
    const float* emb   = (const float*)d_in[0];
    const void*  moves = d_in[1];
    const void*  batch = d_in[2];
    const float* W1    = (const float*)d_in[3];
    const float* b1    = (const float*)d_in[4];
    const float* W2    = (const float*)d_in[5];
    const float* b2    = (const float*)d_in[6];

    int M  = in_sizes[0] / HID;   // 100000
    int NM = in_sizes[1] / 2;     // 500000

    init_kernel<<<1, NG>>>((const int*)moves);

    int n8 = M * HID / 8;
    convert_A_kernel<<<(n8 + 255) / 256, 256>>>(emb, n8);
    convert_W1_kernel<<<(512 * 256 + 255) / 256, 256>>>(W1, W2);

    const int smem_bytes = (128 * PADA + 2 * 128 * PADK) * 2;   // 88064 B
    cudaFuncSetAttribute(hgemm_kernel, cudaFuncAttributeMaxDynamicSharedMemorySize, smem_bytes);
    hgemm_kernel<<<(M + 127) / 128, 256, smem_bytes>>>(b1, M);

    // 4 moves per warp, 8 warps per block -> 32 moves per block
    int gblocks = (NM + 31) / 32;
    gather_logits_kernel<<<gblocks, 256>>>(moves, batch, b2, NM);

    int q = (NM + 3) / 4;
    div_kernel<<<(q + 255) / 256, 256>>>((float*)d_out, NM);
}

// round 12
// speedup vs baseline: 3.5234x; 1.0580x over previous
#include <cuda_runtime.h>
#include <cuda_fp16.h>

#define HID  256
#define NG   512
#define MAXN 100000
#define MAXE 500000
#define PADK 40            // B smem row stride (fp16): 32 data + 8 pad
#define PADA 264           // A smem row stride (fp16): 256 data + 8 pad

// Scratch (device globals)
__device__ __half g_W1h[512 * 256];            // W1 transposed: [(h*256+n)][k]
__device__ __half g_W2h[256];                  // W2 in fp16
__device__ __half g_Ph[(size_t)MAXN * 512];    // P: cols 0..255 = P1+b1, 256..511 = P2
__device__ float  g_e[MAXE];                   // exp(logit)
__device__ int    g_mb[MAXE];
__device__ float  g_segsum[NG];
__device__ int    g_is64;

// ---------------------------------------------------------------------------
// init: zero segsum; thread 0 also detects index dtype
// (int64 => all odd 32-bit words zero for values < 2^31)
// ---------------------------------------------------------------------------
__global__ void init_kernel(const int* __restrict__ moves_i32) {
    int i = threadIdx.x;
    if (i < NG) g_segsum[i] = 0.0f;
    if (i == 0) {
        int acc = 0;
#pragma unroll 8
        for (int k = 1; k < 2048; k += 2) acc |= moves_i32[k];
        g_is64 = (acc == 0) ? 1 : 0;
    }
}

__device__ __forceinline__ long long load_idx(const void* p, size_t i, int is64) {
    if (is64) return ((const long long*)p)[i];
    return (long long)((const int*)p)[i];
}

// ---------------------------------------------------------------------------
// convert W1 -> [n][k] fp16, W2 -> fp16
// ---------------------------------------------------------------------------
__global__ void convert_W1_kernel(const float* __restrict__ W1,
                                  const float* __restrict__ W2) {
    int e = blockIdx.x * blockDim.x + threadIdx.x;   // 0 .. 512*256-1
    if (e < 512 * 256) {
        int r = e >> 8;          // W1 row (feature index) 0..511
        int n = e & 255;         // W1 col (output j)
        int h = r >> 8;          // half 0/1
        int k = r & 255;         // k within half
        g_W1h[(h * 256 + n) * 256 + k] = __float2half(W1[e]);
    }
    if (e < 256) g_W2h[e] = __float2half(W2[e]);
}

// ---------------------------------------------------------------------------
// fp16 GEMM, A-stripe resident + fused fp32->fp16 A conversion:
//   P[M, 512] = emb[M,256] @ W1h^T (+ b1 on cols 0..255), output fp16.
//   One CTA per 128-row stripe. A loaded fp32 from emb, converted, STS once.
//   B streamed via 4-stage cp.async ring (32 tiles of 128x32), ONE sync/tile.
//   256 threads / 8 warps, warp tile 64x32, m16n8k16, ldmatrix.
// ---------------------------------------------------------------------------
__device__ __forceinline__ unsigned smem_u32(const void* p) {
    return (unsigned)__cvta_generic_to_shared(p);
}

__global__ __launch_bounds__(256) void hgemm_kernel(
    const float* __restrict__ emb, const float* __restrict__ b1, int M)
{
    extern __shared__ __half sm[];
    __half* As = sm;                        // 128 x PADA
    __half* Bs = sm + 128 * PADA;           // 4 x 128 x PADK

    int row0 = blockIdx.x * 128;
    int tid  = threadIdx.x;
    int lane = tid & 31;
    int wid  = tid >> 5;
    int wm   = wid & 1;                     // 64-row half
    int wn   = wid >> 1;                    // 32-col quarter

    // ---- B tile issue: tile t -> nblk = t>>3, kt = t&7; 512 chunks, 2/thread
    auto issue_B = [&](int t) {
        int s  = t & 3;
        int nb = t >> 3;
        int kt = t & 7;
#pragma unroll
        for (int i = 0; i < 2; i++) {
            int c = i * 256 + tid;          // 0..511
            int r = c >> 2;                 // 0..127
            int col = (c & 3) * 8;          // 0,8,16,24
            unsigned dst = smem_u32(Bs + s * 128 * PADK + r * PADK + col);
            const __half* src = g_W1h + (size_t)(nb * 128 + r) * 256 + kt * 32 + col;
            asm volatile("cp.async.cg.shared.global [%0], [%1], 16;\n"
                         :: "r"(dst), "l"(src));
        }
        asm volatile("cp.async.commit_group;\n");
    };

    // prefetch first 3 B tiles while we convert A
    issue_B(0);
    issue_B(1);
    issue_B(2);

    // ---- load A stripe fp32 -> fp16 smem (one-time).
    // 128 rows x 256 cols; per thread 16 chunks of 8 elems.
    {
#pragma unroll 4
        for (int i = 0; i < 16; i++) {
            int c = i * 256 + tid;          // 0..4095
            int r = c >> 5;                 // 0..127
            int col = (c & 31) * 8;         // 0..248
            float4 v0 = make_float4(0.f, 0.f, 0.f, 0.f), v1 = v0;
            if (row0 + r < M) {
                const float4* src = (const float4*)(emb + (size_t)(row0 + r) * HID + col);
                v0 = src[0];
                v1 = src[1];
            }
            __half2 h[4];
            h[0] = __floats2half2_rn(v0.x, v0.y);
            h[1] = __floats2half2_rn(v0.z, v0.w);
            h[2] = __floats2half2_rn(v1.x, v1.y);
            h[3] = __floats2half2_rn(v1.z, v1.w);
            *(uint4*)(As + r * PADA + col) = *(const uint4*)h;
        }
    }

    float acc[4][4][4];
#pragma unroll
    for (int i = 0; i < 4; i++)
#pragma unroll
        for (int j = 0; j < 4; j++)
#pragma unroll
            for (int r = 0; r < 4; r++) acc[i][j][r] = 0.0f;

    for (int t = 0; t < 32; t++) {
        // tile t must be complete; most recent (t+1, t+2) may be pending
        if (t < 30)      asm volatile("cp.async.wait_group 2;\n");
        else if (t == 30) asm volatile("cp.async.wait_group 1;\n");
        else              asm volatile("cp.async.wait_group 0;\n");
        __syncthreads();                    // all warps done with buf (t-1)&3; A visible at t=0

        if (t + 3 < 32) issue_B(t + 3);

        const __half* Asb = As + wm * 64 * PADA;
        const __half* Bsb = Bs + (t & 3) * 128 * PADK + wn * 32 * PADK;
        int kt = t & 7;

#pragma unroll
        for (int ks = 0; ks < 2; ks++) {
            int ka = kt * 32 + ks * 16;
            int kb = ks * 16;
            unsigned af[4][4];
            unsigned bf[4][2];
#pragma unroll
            for (int mt = 0; mt < 4; mt++) {
                unsigned addr = smem_u32(Asb + (mt * 16 + (lane & 15)) * PADA + ka + (lane >> 4) * 8);
                asm volatile("ldmatrix.sync.aligned.m8n8.x4.shared.b16 {%0,%1,%2,%3}, [%4];\n"
                             : "=r"(af[mt][0]), "=r"(af[mt][1]), "=r"(af[mt][2]), "=r"(af[mt][3])
                             : "r"(addr));
            }
#pragma unroll
            for (int nt = 0; nt < 4; nt++) {
                unsigned addr = smem_u32(Bsb + (nt * 8 + (lane & 7)) * PADK + kb + ((lane >> 3) & 1) * 8);
                asm volatile("ldmatrix.sync.aligned.m8n8.x2.shared.b16 {%0,%1}, [%2];\n"
                             : "=r"(bf[nt][0]), "=r"(bf[nt][1])
                             : "r"(addr));
            }
#pragma unroll
            for (int mt = 0; mt < 4; mt++)
#pragma unroll
                for (int nt = 0; nt < 4; nt++) {
                    asm volatile(
                        "mma.sync.aligned.m16n8k16.row.col.f32.f16.f16.f32 "
                        "{%0,%1,%2,%3}, {%4,%5,%6,%7}, {%8,%9}, {%0,%1,%2,%3};\n"
                        : "+f"(acc[mt][nt][0]), "+f"(acc[mt][nt][1]),
                          "+f"(acc[mt][nt][2]), "+f"(acc[mt][nt][3])
                        : "r"(af[mt][0]), "r"(af[mt][1]), "r"(af[mt][2]), "r"(af[mt][3]),
                          "r"(bf[nt][0]), "r"(bf[nt][1]));
                }
        }

        if (kt == 7) {
            int nblk = t >> 3;
            int gcol_base = nblk * 128 + wn * 32 + (lane & 3) * 2;
            int grow_base = row0 + wm * 64 + (lane >> 2);
#pragma unroll
            for (int mt = 0; mt < 4; mt++) {
#pragma unroll
                for (int nt = 0; nt < 4; nt++) {
                    int gc = gcol_base + nt * 8;
                    float add0 = 0.0f, add1 = 0.0f;
                    if (nblk < 2) { add0 = b1[gc]; add1 = b1[gc + 1]; }
                    int r0 = grow_base + mt * 16;
                    if (r0 < M)
                        *(__half2*)(g_Ph + (size_t)r0 * 512 + gc) =
                            __floats2half2_rn(acc[mt][nt][0] + add0, acc[mt][nt][1] + add1);
                    if (r0 + 8 < M)
                        *(__half2*)(g_Ph + (size_t)(r0 + 8) * 512 + gc) =
                            __floats2half2_rn(acc[mt][nt][2] + add0, acc[mt][nt][3] + add1);
#pragma unroll
                    for (int r = 0; r < 4; r++) acc[mt][nt][r] = 0.0f;
                }
            }
        }
    }
}

// ---------------------------------------------------------------------------
// gather: 8 lanes per move, 4 moves per warp (MLP=8 independent P loads/lane).
// No max pass: e = exp(logit) accumulated straight into segsum.
// ---------------------------------------------------------------------------
__global__ __launch_bounds__(256) void gather_logits_kernel(
    const void* __restrict__ moves,
    const void* __restrict__ batch,
    const float* __restrict__ b2,
    int NM)
{
    int warp = (blockIdx.x * blockDim.x + threadIdx.x) >> 5;
    int lane = threadIdx.x & 31;
    int grp  = lane >> 3;                   // 0..3
    int q    = lane & 7;                    // 0..7
    int m    = warp * 4 + grp;
    if (m >= NM) return;

    int is64 = g_is64;
    long long s = load_idx(moves, m, is64);
    long long t = load_idx(moves, (size_t)NM + m, is64);

    const uint4* p1 = (const uint4*)(g_Ph + (size_t)s * 512);        // 32 uint4
    const uint4* p2 = (const uint4*)(g_Ph + (size_t)t * 512 + 256);
    const uint4* pw = (const uint4*)g_W2h;

    uint4 u1[4], u2[4], uw[4];
#pragma unroll
    for (int i = 0; i < 4; i++) {
        u1[i] = p1[q + 8 * i];
        u2[i] = p2[q + 8 * i];
        uw[i] = pw[q + 8 * i];
    }

    float acc = 0.0f;
#pragma unroll
    for (int i = 0; i < 4; i++) {
        const __half2* a = (const __half2*)&u1[i];
        const __half2* d = (const __half2*)&u2[i];
        const __half2* w = (const __half2*)&uw[i];
#pragma unroll
        for (int j = 0; j < 4; j++) {
            float2 av = __half22float2(a[j]);
            float2 dv = __half22float2(d[j]);
            float2 wv = __half22float2(w[j]);
            acc += fmaxf(av.x + dv.x, 0.0f) * wv.x;
            acc += fmaxf(av.y + dv.y, 0.0f) * wv.y;
        }
    }

    acc += __shfl_xor_sync(0xffffffffu, acc, 4);
    acc += __shfl_xor_sync(0xffffffffu, acc, 2);
    acc += __shfl_xor_sync(0xffffffffu, acc, 1);

    if (q == 0) {
        float e = expf(acc + b2[0]);
        int g = (int)load_idx(batch, (size_t)s, is64);
        g_e[m] = e;
        g_mb[m] = g;
        atomicAdd(&g_segsum[g], e);
    }
}

// ---------------------------------------------------------------------------
// div: probs = e / (segsum + eps), 4 per thread
// ---------------------------------------------------------------------------
__global__ void div_kernel(float* __restrict__ out, int NM) {
    int i = blockIdx.x * blockDim.x + threadIdx.x;
    int base = i * 4;
    if (base + 3 < NM) {
        float4 e = *(const float4*)(g_e + base);
        int4   g = *(const int4*)(g_mb + base);
        float4 r;
        r.x = e.x / (g_segsum[g.x] + 1e-16f);
        r.y = e.y / (g_segsum[g.y] + 1e-16f);
        r.z = e.z / (g_segsum[g.z] + 1e-16f);
        r.w = e.w / (g_segsum[g.w] + 1e-16f);
        *(float4*)(out + base) = r;
    } else {
        for (int k = base; k < NM; k++)
            out[k] = g_e[k] / (g_segsum[g_mb[k]] + 1e-16f);
    }
}

// ---------------------------------------------------------------------------
extern "C" void kernel_launch(void* const* d_in, const int* in_sizes, int n_in,
                              void* d_out, int out_size)
{
    const float* emb   = (const float*)d_in[0];
    const void*  moves = d_in[1];
    const void*  batch = d_in[2];
    const float* W1    = (const float*)d_in[3];
    const float* b1    = (const float*)d_in[4];
    const float* W2    = (const float*)d_in[5];
    const float* b2    = (const float*)d_in[6];

    int M  = in_sizes[0] / HID;   // 100000
    int NM = in_sizes[1] / 2;     // 500000

    init_kernel<<<1, NG>>>((const int*)moves);
    convert_W1_kernel<<<(512 * 256 + 255) / 256, 256>>>(W1, W2);

    const int smem_bytes = (128 * PADA + 4 * 128 * PADK) * 2;   // 108544 B
    cudaFuncSetAttribute(hgemm_kernel, cudaFuncAttributeMaxDynamicSharedMemorySize, smem_bytes);
    hgemm_kernel<<<(M + 127) / 128, 256, smem_bytes>>>(emb, b1, M);

    int gblocks = (NM + 31) / 32;
    gather_logits_kernel<<<gblocks, 256>>>(moves, batch, b2, NM);

    int q = (NM + 3) / 4;
    div_kernel<<<(q + 255) / 256, 256>>>((float*)d_out, NM);
}